// round 3
// baseline (speedup 1.0000x reference)
#include <cuda_runtime.h>
#include <math.h>
#include <stdint.h>

#define H 2048
#define E 64
#define S 4096
#define B 2
#define SW 1024
#define NEGF (-3.4028234663852886e38f)   // -FLT_MAX == finfo(float32).min

#define OFF_SLID 33554432ull             // 2*4096*4096
#define OFF_W    67108864ull
#define OFF_I    67141632ull             // OFF_W + 8192*4

#define GATE_BLOCKS 128
#define MASK_BLOCKS 2048                 // B * S / 4 q-rows per block

// scratch (no allocations allowed)
__device__ float g_w2[E * H];            // proj_w * scale * H^-0.5
__device__ int4  g_qmeta[B * S];         // {flo, s1lo, v2lo, v2hi} per q

// ---------------------------------------------------------------------------
// K0: fold scale and H^-0.5 into proj_w
// ---------------------------------------------------------------------------
__global__ void fold_w_kernel(const float* __restrict__ pw,
                              const float* __restrict__ scale) {
    int i = blockIdx.x * 256 + threadIdx.x;     // 512*256 = E*H
    g_w2[i] = pw[i] * scale[i & (H - 1)] * 0.022097086912079608f; // 1/sqrt(2048)
}

// ---------------------------------------------------------------------------
// K1: per-q interval metadata. One block (1024 thr) per batch, 4 positions/thr.
//   flo  = doc start (or S if padding)
//   s1lo = max(flo, q-SW+1)            (sliding causal-window start)
//   [v2lo, v2hi] = vision-group run ∩ doc interval (empty: {S,-1})
// ---------------------------------------------------------------------------
__global__ __launch_bounds__(1024) void prep_kernel(const int* __restrict__ packed,
                                                    const int* __restrict__ mm) {
    __shared__ int ss[1024];
    const int INF = 0x7fffffff;
    int b = blockIdx.x, t = threadIdx.x;
    const int* pk = packed + b * S;
    const int* m  = mm + b * S;
    int base = t * 4;

    int p[4], mv[4];
    #pragma unroll
    for (int j = 0; j < 4; j++) { p[j] = pk[base + j]; mv[j] = m[base + j]; }
    int pprev = (base > 0) ? pk[base - 1] : -123456;
    int pnext = (base + 4 < S) ? pk[base + 4] : -123456;
    int mprev = (base > 0) ? m[base - 1] : 0;
    int mnext = (base + 4 < S) ? m[base + 4] : 0;

    bool v[4];
    #pragma unroll
    for (int j = 0; j < 4; j++) v[j] = (mv[j] == 1) | (mv[j] == 2);
    bool vprev = (mprev == 1) | (mprev == 2);
    bool vnext = (mnext == 1) | (mnext == 2);

    // ---- forward inclusive max scan: doc start ----
    int dloc[4];
    {
        int run = -1;
        #pragma unroll
        for (int j = 0; j < 4; j++) {
            bool f = (j == 0) ? (base == 0 || p[0] != pprev) : (p[j] != p[j - 1]);
            if (f) run = base + j;
            dloc[j] = run;
        }
        ss[t] = run; __syncthreads();
        for (int off = 1; off < 1024; off <<= 1) {
            int xv = (t >= off) ? ss[t - off] : -1; __syncthreads();
            if (xv > ss[t]) ss[t] = xv; __syncthreads();
        }
        int excl = (t > 0) ? ss[t - 1] : -1;
        #pragma unroll
        for (int j = 0; j < 4; j++) if (excl > dloc[j]) dloc[j] = excl;
    }
    __syncthreads();

    // ---- forward inclusive max scan: vision run start ----
    int vloc[4];
    {
        int run = -1;
        #pragma unroll
        for (int j = 0; j < 4; j++) {
            bool pvj = (j == 0) ? vprev : v[j - 1];
            bool f = v[j] && !pvj;
            if (f) run = base + j;
            vloc[j] = run;
        }
        ss[t] = run; __syncthreads();
        for (int off = 1; off < 1024; off <<= 1) {
            int xv = (t >= off) ? ss[t - off] : -1; __syncthreads();
            if (xv > ss[t]) ss[t] = xv; __syncthreads();
        }
        int excl = (t > 0) ? ss[t - 1] : -1;
        #pragma unroll
        for (int j = 0; j < 4; j++) if (excl > vloc[j]) vloc[j] = excl;
    }
    __syncthreads();

    // ---- backward inclusive min scan: doc end ----
    int dend[4];
    {
        int run = INF;
        #pragma unroll
        for (int jj = 3; jj >= 0; jj--) {
            bool f = (jj == 3) ? (base + 4 >= S || p[3] != pnext) : (p[jj] != p[jj + 1]);
            if (f) run = base + jj;
            dend[jj] = run;
        }
        ss[t] = run; __syncthreads();
        for (int off = 1; off < 1024; off <<= 1) {
            int xv = (t + off < 1024) ? ss[t + off] : INF; __syncthreads();
            if (xv < ss[t]) ss[t] = xv; __syncthreads();
        }
        int excl = (t < 1023) ? ss[t + 1] : INF;
        #pragma unroll
        for (int j = 0; j < 4; j++) if (excl < dend[j]) dend[j] = excl;
    }
    __syncthreads();

    // ---- backward inclusive min scan: vision run end ----
    int vend[4];
    {
        int run = INF;
        #pragma unroll
        for (int jj = 3; jj >= 0; jj--) {
            bool nvj = (jj == 3) ? vnext : v[jj + 1];
            bool f = v[jj] && !nvj;
            if (f) run = base + jj;
            vend[jj] = run;
        }
        ss[t] = run; __syncthreads();
        for (int off = 1; off < 1024; off <<= 1) {
            int xv = (t + off < 1024) ? ss[t + off] : INF; __syncthreads();
            if (xv < ss[t]) ss[t] = xv; __syncthreads();
        }
        int excl = (t < 1023) ? ss[t + 1] : INF;
        #pragma unroll
        for (int j = 0; j < 4; j++) if (excl < vend[j]) vend[j] = excl;
    }

    #pragma unroll
    for (int j = 0; j < 4; j++) {
        int q = base + j;
        int4 mt;
        if (p[j] <= 0) {
            mt.x = S; mt.y = S; mt.z = S; mt.w = -1;
        } else {
            int flo = dloc[j];
            mt.x = flo;
            int s1 = q - (SW - 1);
            mt.y = (s1 > flo) ? s1 : flo;
            if (v[j]) {
                int vl = vloc[j]; if (flo > vl) vl = flo;
                int vh = vend[j]; if (dend[j] < vh) vh = dend[j];
                mt.z = vl; mt.w = vh;
            } else {
                mt.z = S; mt.w = -1;
            }
        }
        g_qmeta[b * S + q] = mt;
    }
}

// ---------------------------------------------------------------------------
// FFMA2 helper: packed fp32x2 FMA (sm_100+)
// ---------------------------------------------------------------------------
__device__ __forceinline__ void ffma2(unsigned long long& d,
                                      unsigned long long a,
                                      unsigned long long b) {
    asm("fma.rn.f32x2 %0, %1, %2, %0;" : "+l"(d) : "l"(a), "l"(b));
}

// ---------------------------------------------------------------------------
// K2: fused heterogeneous kernel.
//   blocks [0, 128):      gate GEMM (64 rows x 64 experts, f32x2 FMA) + top-4
//   blocks [128, 2176):   mask writer (4 q-rows per block, interval predicates)
// ---------------------------------------------------------------------------
__global__ __launch_bounds__(256) void fused_kernel(const float* __restrict__ x,
                                                    float* __restrict__ out) {
    if (blockIdx.x < GATE_BLOCKS) {
        // ================= GATE =================
        __shared__ __align__(16) float Xs2[32][132];  // k-major, x duplicated pairs
        __shared__ __align__(16) float Ws[32][68];
        __shared__ float s_l[64][68];

        int bm  = blockIdx.x;
        int tid = threadIdx.x;
        int w   = tid >> 5, lane = tid & 31;
        int tr  = tid >> 4, tc = tid & 15;
        const float* xb = x + (size_t)bm * 64 * H;

        unsigned long long acc[4][2] = {};
        float ssacc[8] = {};

        uint32_t xs_base = (uint32_t)__cvta_generic_to_shared(&Xs2[0][0]);
        uint32_t ws_base = (uint32_t)__cvta_generic_to_shared(&Ws[0][0]);
        uint32_t xaddr0 = xs_base + (uint32_t)(8 * tr) * 4u;
        uint32_t waddr0 = ws_base + (uint32_t)(tc * 4) * 4u;

        for (int kt = 0; kt < 64; kt++) {
            __syncthreads();
            #pragma unroll
            for (int i = 0; i < 8; i++) {
                int row = (tid >> 5) + 8 * i;       // warp w -> rows w+8i
                int k   = lane;
                float vv = xb[(size_t)row * H + kt * 32 + k];
                ssacc[i] += vv * vv;
                *(float2*)&Xs2[k][2 * row] = make_float2(vv, vv);
                Ws[k][row] = g_w2[row * H + kt * 32 + k];  // row == expert
            }
            __syncthreads();

            uint32_t xa = xaddr0, wa = waddr0;
            #pragma unroll
            for (int k = 0; k < 32; k++) {
                unsigned long long x01, x23, x45, x67, w01, w23;
                asm volatile("ld.shared.v2.b64 {%0,%1},[%2];"
                             : "=l"(x01), "=l"(x23) : "r"(xa));
                asm volatile("ld.shared.v2.b64 {%0,%1},[%2];"
                             : "=l"(x45), "=l"(x67) : "r"(xa + 16));
                asm volatile("ld.shared.v2.b64 {%0,%1},[%2];"
                             : "=l"(w01), "=l"(w23) : "r"(wa));
                ffma2(acc[0][0], x01, w01); ffma2(acc[0][1], x01, w23);
                ffma2(acc[1][0], x23, w01); ffma2(acc[1][1], x23, w23);
                ffma2(acc[2][0], x45, w01); ffma2(acc[2][1], x45, w23);
                ffma2(acc[3][0], x67, w01); ffma2(acc[3][1], x67, w23);
                xa += 132 * 4;
                wa += 68 * 4;
            }
        }

        __syncthreads();
        #pragma unroll
        for (int i = 0; i < 4; i++) {
            #pragma unroll
            for (int pp = 0; pp < 2; pp++) {
                float lo, hi;
                asm("mov.b64 {%0,%1},%2;" : "=f"(lo), "=f"(hi) : "l"(acc[i][pp]));
                s_l[tr * 4 + i][tc * 4 + 2 * pp]     = lo;
                s_l[tr * 4 + i][tc * 4 + 2 * pp + 1] = hi;
            }
        }
        __syncthreads();

        // per-row top-4 + renormalized softmax (== softmax over top-4 logits)
        #pragma unroll
        for (int i = 0; i < 8; i++) {
            int rr = w + 8 * i;
            float s = ssacc[i];
            #pragma unroll
            for (int o = 16; o; o >>= 1) s += __shfl_xor_sync(0xffffffffu, s, o);
            float r = rsqrtf(s * (1.0f / H) + 1e-6f);
            float v0 = r * s_l[rr][lane];
            float v1 = r * s_l[rr][lane + 32];
            float vals[4]; int ids[4];
            #pragma unroll
            for (int t4 = 0; t4 < 4; t4++) {
                float cv; int ci;
                if (v1 > v0) { cv = v1; ci = lane + 32; }
                else         { cv = v0; ci = lane; }   // tie -> smaller index
                #pragma unroll
                for (int o = 16; o; o >>= 1) {
                    float ov = __shfl_xor_sync(0xffffffffu, cv, o);
                    int   oi = __shfl_xor_sync(0xffffffffu, ci, o);
                    if (ov > cv || (ov == cv && oi < ci)) { cv = ov; ci = oi; }
                }
                vals[t4] = cv; ids[t4] = ci;
                if (ci < 32) { if (lane == ci)      v0 = -3.4e38f; }
                else         { if (lane == ci - 32) v1 = -3.4e38f; }
            }
            if (lane == 0) {
                int row = bm * 64 + rr;
                float mmax = vals[0];
                float e0 = expf(vals[0] - mmax), e1 = expf(vals[1] - mmax);
                float e2 = expf(vals[2] - mmax), e3 = expf(vals[3] - mmax);
                float inv = 1.0f / (e0 + e1 + e2 + e3);
                float* ow = out + OFF_W + (size_t)row * 4;
                float* oi = out + OFF_I + (size_t)row * 4;
                ow[0] = e0 * inv; ow[1] = e1 * inv; ow[2] = e2 * inv; ow[3] = e3 * inv;
                oi[0] = (float)ids[0]; oi[1] = (float)ids[1];
                oi[2] = (float)ids[2]; oi[3] = (float)ids[3];
            }
        }
    } else {
        // ================= MASK =================
        int mb = blockIdx.x - GATE_BLOCKS;      // 0 .. 2047
        int b  = mb >> 10;
        int q0 = (mb & 1023) << 2;
        int tid = threadIdx.x;

        float* fullb = out + (size_t)b * S * S;
        float* slidb = out + OFF_SLID + (size_t)b * S * S;

        #pragma unroll
        for (int qi = 0; qi < 4; qi++) {
            int q = q0 + qi;
            int4 mt = g_qmeta[b * S + q];       // {flo, s1lo, v2lo, v2hi}
            float4* fo = (float4*)(fullb + (size_t)q * S);
            float4* so = (float4*)(slidb + (size_t)q * S);
            #pragma unroll
            for (int it = 0; it < 4; it++) {
                int k4 = tid + it * 256;
                int kv = k4 * 4;
                float4 f, sl;
                {
                    int k = kv + 0;
                    bool fb = (k >= mt.x) & (k <= q);
                    bool sb = ((k >= mt.y) & (k <= q)) | ((k >= mt.z) & (k <= mt.w));
                    f.x = fb ? 0.0f : NEGF; sl.x = sb ? 0.0f : NEGF;
                }
                {
                    int k = kv + 1;
                    bool fb = (k >= mt.x) & (k <= q);
                    bool sb = ((k >= mt.y) & (k <= q)) | ((k >= mt.z) & (k <= mt.w));
                    f.y = fb ? 0.0f : NEGF; sl.y = sb ? 0.0f : NEGF;
                }
                {
                    int k = kv + 2;
                    bool fb = (k >= mt.x) & (k <= q);
                    bool sb = ((k >= mt.y) & (k <= q)) | ((k >= mt.z) & (k <= mt.w));
                    f.z = fb ? 0.0f : NEGF; sl.z = sb ? 0.0f : NEGF;
                }
                {
                    int k = kv + 3;
                    bool fb = (k >= mt.x) & (k <= q);
                    bool sb = ((k >= mt.y) & (k <= q)) | ((k >= mt.z) & (k <= mt.w));
                    f.w = fb ? 0.0f : NEGF; sl.w = sb ? 0.0f : NEGF;
                }
                __stcs(&fo[k4], f);
                __stcs(&so[k4], sl);
            }
        }
    }
}

// ---------------------------------------------------------------------------
extern "C" void kernel_launch(void* const* d_in, const int* in_sizes, int n_in,
                              void* d_out, int out_size) {
    const float* x      = (const float*)d_in[0];
    const int*   packed = (const int*)d_in[1];
    const int*   mm     = (const int*)d_in[2];
    const float* scale  = (const float*)d_in[3];
    const float* pw     = (const float*)d_in[4];
    float* out = (float*)d_out;

    fold_w_kernel<<<512, 256>>>(pw, scale);
    prep_kernel<<<B, 1024>>>(packed, mm);
    fused_kernel<<<GATE_BLOCKS + MASK_BLOCKS, 256>>>(x, out);
}

// round 4
// speedup vs baseline: 1.3284x; 1.3284x over previous
#include <cuda_runtime.h>
#include <math.h>
#include <stdint.h>

#define H 2048
#define E 64
#define S 4096
#define B 2
#define SW 1024
#define NEGF (-3.4028234663852886e38f)   // -FLT_MAX == finfo(float32).min

#define OFF_SLID 33554432ull             // 2*4096*4096
#define OFF_W    67108864ull
#define OFF_I    67141632ull             // OFF_W + 8192*4

#define RSQRT_H 0.022097086912079608f    // 1/sqrt(2048)

// scratch (no allocations allowed)
__device__ int4 g_qmeta[B * S];          // {flo, s1lo, v2lo, v2hi} per q

// ---------------------------------------------------------------------------
// K1: per-q interval metadata. One block (1024 thr) per batch, 4 positions/thr.
// ---------------------------------------------------------------------------
__global__ __launch_bounds__(1024) void prep_kernel(const int* __restrict__ packed,
                                                    const int* __restrict__ mm) {
    __shared__ int ss[1024];
    const int INF = 0x7fffffff;
    int b = blockIdx.x, t = threadIdx.x;
    const int* pk = packed + b * S;
    const int* m  = mm + b * S;
    int base = t * 4;

    int p[4], mv[4];
    #pragma unroll
    for (int j = 0; j < 4; j++) { p[j] = pk[base + j]; mv[j] = m[base + j]; }
    int pprev = (base > 0) ? pk[base - 1] : -123456;
    int pnext = (base + 4 < S) ? pk[base + 4] : -123456;
    int mprev = (base > 0) ? m[base - 1] : 0;
    int mnext = (base + 4 < S) ? m[base + 4] : 0;

    bool v[4];
    #pragma unroll
    for (int j = 0; j < 4; j++) v[j] = (mv[j] == 1) | (mv[j] == 2);
    bool vprev = (mprev == 1) | (mprev == 2);
    bool vnext = (mnext == 1) | (mnext == 2);

    // forward inclusive max scan: doc start
    int dloc[4];
    {
        int run = -1;
        #pragma unroll
        for (int j = 0; j < 4; j++) {
            bool f = (j == 0) ? (base == 0 || p[0] != pprev) : (p[j] != p[j - 1]);
            if (f) run = base + j;
            dloc[j] = run;
        }
        ss[t] = run; __syncthreads();
        for (int off = 1; off < 1024; off <<= 1) {
            int xv = (t >= off) ? ss[t - off] : -1; __syncthreads();
            if (xv > ss[t]) ss[t] = xv; __syncthreads();
        }
        int excl = (t > 0) ? ss[t - 1] : -1;
        #pragma unroll
        for (int j = 0; j < 4; j++) if (excl > dloc[j]) dloc[j] = excl;
    }
    __syncthreads();

    // forward inclusive max scan: vision run start
    int vloc[4];
    {
        int run = -1;
        #pragma unroll
        for (int j = 0; j < 4; j++) {
            bool pvj = (j == 0) ? vprev : v[j - 1];
            bool f = v[j] && !pvj;
            if (f) run = base + j;
            vloc[j] = run;
        }
        ss[t] = run; __syncthreads();
        for (int off = 1; off < 1024; off <<= 1) {
            int xv = (t >= off) ? ss[t - off] : -1; __syncthreads();
            if (xv > ss[t]) ss[t] = xv; __syncthreads();
        }
        int excl = (t > 0) ? ss[t - 1] : -1;
        #pragma unroll
        for (int j = 0; j < 4; j++) if (excl > vloc[j]) vloc[j] = excl;
    }
    __syncthreads();

    // backward inclusive min scan: doc end
    int dend[4];
    {
        int run = INF;
        #pragma unroll
        for (int jj = 3; jj >= 0; jj--) {
            bool f = (jj == 3) ? (base + 4 >= S || p[3] != pnext) : (p[jj] != p[jj + 1]);
            if (f) run = base + jj;
            dend[jj] = run;
        }
        ss[t] = run; __syncthreads();
        for (int off = 1; off < 1024; off <<= 1) {
            int xv = (t + off < 1024) ? ss[t + off] : INF; __syncthreads();
            if (xv < ss[t]) ss[t] = xv; __syncthreads();
        }
        int excl = (t < 1023) ? ss[t + 1] : INF;
        #pragma unroll
        for (int j = 0; j < 4; j++) if (excl < dend[j]) dend[j] = excl;
    }
    __syncthreads();

    // backward inclusive min scan: vision run end
    int vend[4];
    {
        int run = INF;
        #pragma unroll
        for (int jj = 3; jj >= 0; jj--) {
            bool nvj = (jj == 3) ? vnext : v[jj + 1];
            bool f = v[jj] && !nvj;
            if (f) run = base + jj;
            vend[jj] = run;
        }
        ss[t] = run; __syncthreads();
        for (int off = 1; off < 1024; off <<= 1) {
            int xv = (t + off < 1024) ? ss[t + off] : INF; __syncthreads();
            if (xv < ss[t]) ss[t] = xv; __syncthreads();
        }
        int excl = (t < 1023) ? ss[t + 1] : INF;
        #pragma unroll
        for (int j = 0; j < 4; j++) if (excl < vend[j]) vend[j] = excl;
    }

    #pragma unroll
    for (int j = 0; j < 4; j++) {
        int q = base + j;
        int4 mt;
        if (p[j] <= 0) {
            mt.x = S; mt.y = S; mt.z = S; mt.w = -1;
        } else {
            int flo = dloc[j];
            mt.x = flo;
            int s1 = q - (SW - 1);
            mt.y = (s1 > flo) ? s1 : flo;
            if (v[j]) {
                int vl = vloc[j]; if (flo > vl) vl = flo;
                int vh = vend[j]; if (dend[j] < vh) vh = dend[j];
                mt.z = vl; mt.w = vh;
            } else {
                mt.z = S; mt.w = -1;
            }
        }
        g_qmeta[b * S + q] = mt;
    }
}

// ---------------------------------------------------------------------------
// FFMA2 helper: packed fp32x2 FMA (sm_100+)
// ---------------------------------------------------------------------------
__device__ __forceinline__ void ffma2(unsigned long long& d,
                                      unsigned long long a,
                                      unsigned long long b) {
    asm("fma.rn.f32x2 %0, %1, %2, %0;" : "+l"(d) : "l"(a), "l"(b));
}

// ---------------------------------------------------------------------------
// K2: gate. 128 blocks x 64 rows x 64 experts, f32x2 FMA, double-buffered
// register prefetch, scale folded into W tile store, fused RMS, top-4.
// ---------------------------------------------------------------------------
__global__ __launch_bounds__(256) void gate_kernel(const float* __restrict__ x,
                                                   const float* __restrict__ scale,
                                                   const float* __restrict__ pw,
                                                   float* __restrict__ out) {
    __shared__ __align__(16) float Xs2[2][32][132];  // k-major, duplicated pairs
    __shared__ __align__(16) float Ws[2][32][68];
    __shared__ float s_l[64][68];

    int bm  = blockIdx.x;
    int tid = threadIdx.x;
    int w   = tid >> 5, lane = tid & 31;
    int tr  = tid >> 4, tc = tid & 15;
    const float* xb = x + (size_t)bm * 64 * H;

    unsigned long long acc[4][2] = {};
    float ssacc[8] = {};
    float rx[8], rw[8], rscale;

    // prologue: tile 0 into registers
    rscale = scale[lane] * RSQRT_H;
    #pragma unroll
    for (int i = 0; i < 8; i++) {
        int row = w + 8 * i;
        rx[i] = xb[(size_t)row * H + lane];
        rw[i] = pw[row * H + lane];          // row == expert
    }

    uint32_t xs0 = (uint32_t)__cvta_generic_to_shared(&Xs2[0][0][0]);
    uint32_t ws0 = (uint32_t)__cvta_generic_to_shared(&Ws[0][0][0]);

    for (int kt = 0; kt < 64; kt++) {
        int p = kt & 1;
        // store current tile
        #pragma unroll
        for (int i = 0; i < 8; i++) {
            int row = w + 8 * i;
            float vv = rx[i];
            ssacc[i] += vv * vv;
            *(float2*)&Xs2[p][lane][2 * row] = make_float2(vv, vv);
            Ws[p][lane][row] = rw[i] * rscale;
        }
        __syncthreads();
        // prefetch next tile into registers (overlaps compute below)
        if (kt < 63) {
            int k0 = (kt + 1) * 32 + lane;
            float ns = scale[k0];
            #pragma unroll
            for (int i = 0; i < 8; i++) {
                int row = w + 8 * i;
                rx[i] = xb[(size_t)row * H + k0];
                rw[i] = pw[row * H + k0];
            }
            rscale = ns * RSQRT_H;
        }
        // compute
        uint32_t xa = xs0 + (uint32_t)p * (32 * 132 * 4) + (uint32_t)(8 * tr) * 4u;
        uint32_t wa = ws0 + (uint32_t)p * (32 * 68 * 4) + (uint32_t)(tc * 4) * 4u;
        #pragma unroll
        for (int k = 0; k < 32; k++) {
            unsigned long long x01, x23, x45, x67, w01, w23;
            asm volatile("ld.shared.v2.b64 {%0,%1},[%2];"
                         : "=l"(x01), "=l"(x23) : "r"(xa));
            asm volatile("ld.shared.v2.b64 {%0,%1},[%2];"
                         : "=l"(x45), "=l"(x67) : "r"(xa + 16));
            asm volatile("ld.shared.v2.b64 {%0,%1},[%2];"
                         : "=l"(w01), "=l"(w23) : "r"(wa));
            ffma2(acc[0][0], x01, w01); ffma2(acc[0][1], x01, w23);
            ffma2(acc[1][0], x23, w01); ffma2(acc[1][1], x23, w23);
            ffma2(acc[2][0], x45, w01); ffma2(acc[2][1], x45, w23);
            ffma2(acc[3][0], x67, w01); ffma2(acc[3][1], x67, w23);
            xa += 132 * 4;
            wa += 68 * 4;
        }
        __syncthreads();
    }

    #pragma unroll
    for (int i = 0; i < 4; i++) {
        #pragma unroll
        for (int pp = 0; pp < 2; pp++) {
            float lo, hi;
            asm("mov.b64 {%0,%1},%2;" : "=f"(lo), "=f"(hi) : "l"(acc[i][pp]));
            s_l[tr * 4 + i][tc * 4 + 2 * pp]     = lo;
            s_l[tr * 4 + i][tc * 4 + 2 * pp + 1] = hi;
        }
    }
    __syncthreads();

    // per-row top-4 + renormalized softmax (== softmax over top-4 logits)
    #pragma unroll
    for (int i = 0; i < 8; i++) {
        int rr = w + 8 * i;
        float s = ssacc[i];
        #pragma unroll
        for (int o = 16; o; o >>= 1) s += __shfl_xor_sync(0xffffffffu, s, o);
        float r = rsqrtf(s * (1.0f / H) + 1e-6f);
        float v0 = r * s_l[rr][lane];
        float v1 = r * s_l[rr][lane + 32];
        float vals[4]; int ids[4];
        #pragma unroll
        for (int t4 = 0; t4 < 4; t4++) {
            float cv; int ci;
            if (v1 > v0) { cv = v1; ci = lane + 32; }
            else         { cv = v0; ci = lane; }   // tie -> smaller index
            #pragma unroll
            for (int o = 16; o; o >>= 1) {
                float ov = __shfl_xor_sync(0xffffffffu, cv, o);
                int   oi = __shfl_xor_sync(0xffffffffu, ci, o);
                if (ov > cv || (ov == cv && oi < ci)) { cv = ov; ci = oi; }
            }
            vals[t4] = cv; ids[t4] = ci;
            if (ci < 32) { if (lane == ci)      v0 = -3.4e38f; }
            else         { if (lane == ci - 32) v1 = -3.4e38f; }
        }
        if (lane == 0) {
            int row = bm * 64 + rr;
            float mmax = vals[0];
            float e0 = expf(vals[0] - mmax), e1 = expf(vals[1] - mmax);
            float e2 = expf(vals[2] - mmax), e3 = expf(vals[3] - mmax);
            float inv = 1.0f / (e0 + e1 + e2 + e3);
            float* ow = out + OFF_W + (size_t)row * 4;
            float* oi = out + OFF_I + (size_t)row * 4;
            ow[0] = e0 * inv; ow[1] = e1 * inv; ow[2] = e2 * inv; ow[3] = e3 * inv;
            oi[0] = (float)ids[0]; oi[1] = (float)ids[1];
            oi[2] = (float)ids[2]; oi[3] = (float)ids[3];
        }
    }
}

// ---------------------------------------------------------------------------
// K3: mask writer. 2048 blocks x 4 q-rows, interval predicates, streaming st.
// ---------------------------------------------------------------------------
__global__ __launch_bounds__(256) void mask_kernel(float* __restrict__ out) {
    int mb = blockIdx.x;                    // 0 .. 2047
    int b  = mb >> 10;
    int q0 = (mb & 1023) << 2;
    int tid = threadIdx.x;

    float* fullb = out + (size_t)b * S * S;
    float* slidb = out + OFF_SLID + (size_t)b * S * S;

    #pragma unroll
    for (int qi = 0; qi < 4; qi++) {
        int q = q0 + qi;
        int4 mt = g_qmeta[b * S + q];       // {flo, s1lo, v2lo, v2hi}
        float4* fo = (float4*)(fullb + (size_t)q * S);
        float4* so = (float4*)(slidb + (size_t)q * S);
        #pragma unroll
        for (int it = 0; it < 4; it++) {
            int k4 = tid + it * 256;
            int kv = k4 * 4;
            float4 f, sl;
            #pragma unroll
            for (int j = 0; j < 4; j++) {
                int k = kv + j;
                bool fb = (k >= mt.x) & (k <= q);
                bool sb = ((k >= mt.y) & (k <= q)) | ((k >= mt.z) & (k <= mt.w));
                (&f.x)[j]  = fb ? 0.0f : NEGF;
                (&sl.x)[j] = sb ? 0.0f : NEGF;
            }
            __stcs(&fo[k4], f);
            __stcs(&so[k4], sl);
        }
    }
}

// ---------------------------------------------------------------------------
extern "C" void kernel_launch(void* const* d_in, const int* in_sizes, int n_in,
                              void* d_out, int out_size) {
    const float* x      = (const float*)d_in[0];
    const int*   packed = (const int*)d_in[1];
    const int*   mm     = (const int*)d_in[2];
    const float* scale  = (const float*)d_in[3];
    const float* pw     = (const float*)d_in[4];
    float* out = (float*)d_out;

    prep_kernel<<<B, 1024>>>(packed, mm);
    gate_kernel<<<128, 256>>>(x, scale, pw, out);
    mask_kernel<<<2048, 256>>>(out);
}